// round 3
// baseline (speedup 1.0000x reference)
#include <cuda_runtime.h>
#include <math.h>

// EstimateAdj: out = diag(1/rowsum(A*B + I)) @ (A*B + I), N=8192.
// One CTA per row; single read of A,B; single write of out.
// R3: streaming cache hints (evict-first) on all loads/stores; diagonal
//     handled algebraically (rowsum = sum(A*B)+1; output diag += rinv)
//     so the hot load loop has no branch.

#define N 8192
#define N4 (N / 4)            // 2048 float4 per row
#define TPB 512
#define V_PER_T (N4 / TPB)    // 4 float4 per thread
#define NWARPS (TPB / 32)     // 16

__device__ __forceinline__ float4 ldcs4(const float4* p) {
    float4 v;
    asm volatile("ld.global.cs.v4.f32 {%0,%1,%2,%3}, [%4];"
                 : "=f"(v.x), "=f"(v.y), "=f"(v.z), "=f"(v.w) : "l"(p));
    return v;
}

__device__ __forceinline__ void stcs4(float4* p, float4 v) {
    asm volatile("st.global.cs.v4.f32 [%0], {%1,%2,%3,%4};"
                 :: "l"(p), "f"(v.x), "f"(v.y), "f"(v.z), "f"(v.w) : "memory");
}

__global__ __launch_bounds__(TPB, 3)
void estimate_adj_kernel(const float4* __restrict__ A,
                         const float4* __restrict__ B,
                         float4* __restrict__ out) {
    const int row = blockIdx.x;
    const long base = (long)row * N4;
    const int tid = threadIdx.x;

    float4 p[V_PER_T];
    float sum = 0.0f;

    // Branch-free load + multiply. Coalesced, front-batched loads.
    #pragma unroll
    for (int j = 0; j < V_PER_T; j++) {
        const int idx = tid + j * TPB;   // 0..2047
        float4 a = ldcs4(A + base + idx);
        float4 b = ldcs4(B + base + idx);
        float4 m;
        m.x = a.x * b.x;
        m.y = a.y * b.y;
        m.z = a.z * b.z;
        m.w = a.w * b.w;
        p[j] = m;
        sum += (m.x + m.y) + (m.z + m.w);
    }

    // Warp reduction
    #pragma unroll
    for (int off = 16; off > 0; off >>= 1)
        sum += __shfl_xor_sync(0xFFFFFFFFu, sum, off);

    __shared__ float warp_sums[NWARPS];
    const int lane = tid & 31;
    const int wid = tid >> 5;
    if (lane == 0) warp_sums[wid] = sum;
    __syncthreads();

    // Every thread finishes the reduction itself (no second barrier).
    // Identity contributes exactly +1 to every rowsum.
    float total = 1.0f;
    #pragma unroll
    for (int w = 0; w < NWARPS; w++) total += warp_sums[w];
    float rinv = 1.0f / total;
    if (isinf(rinv)) rinv = 0.0f;

    // Scale and store from registers; diagonal fixup: out_diag += rinv.
    const int diag4 = row >> 2;          // float4 index of diagonal element
    #pragma unroll
    for (int j = 0; j < V_PER_T; j++) {
        const int idx = tid + j * TPB;
        float4 m = p[j];
        m.x *= rinv; m.y *= rinv; m.z *= rinv; m.w *= rinv;
        if (idx == diag4) {
            ((float*)&m)[row & 3] += rinv;
        }
        stcs4(out + base + idx, m);
    }
}

extern "C" void kernel_launch(void* const* d_in, const int* in_sizes, int n_in,
                              void* d_out, int out_size) {
    const float4* A = (const float4*)d_in[0];   // estimated_adj
    const float4* B = (const float4*)d_in[1];   // ori
    float4* out = (float4*)d_out;
    estimate_adj_kernel<<<N, TPB>>>(A, B, out);
}